// round 1
// baseline (speedup 1.0000x reference)
#include <cuda_runtime.h>
#include <math.h>

// Problem constants
#define B_   4
#define NA_  64
#define T_   128
#define D_   128
#define H_   8
#define DH_  16
#define L_   3
#define DFF_ 512
#define E_   65536
#define NN_  (T_ * NA_)        // 8192
#define R_   (B_ * NA_ * T_)   // 32768 rows
#define EPSV 1e-5f

// ---------------- scratch (device globals; no allocation allowed) ----------------
__device__ __align__(256) float d_x   [R_ * D_];
__device__ __align__(256) float d_oute[R_ * D_];
__device__ __align__(256) float d_q   [R_ * D_];
__device__ __align__(256) float d_k   [R_ * D_];
__device__ __align__(256) float d_v   [R_ * D_];
__device__ __align__(256) float d_h1  [R_ * D_];
__device__ __align__(256) float d_tmp [R_ * D_];
__device__ __align__(256) float d_ff  [R_ * DFF_];
__device__ __align__(256) float d_s   [B_ * NN_];
__device__ __align__(256) float d_g   [B_ * NN_];
__device__ double d_stats[2];

// ---------------- kernel 1: hist projection + positional encoding ----------------
// x = feat(.,3) @ hist_w(3,D) + hist_b ; out_e = x + PE(t,d)
__global__ void hist_pe_kernel(const float* __restrict__ feat,
                               const float* __restrict__ hw,
                               const float* __restrict__ hb)
{
    int idx = blockIdx.x * blockDim.x + threadIdx.x;
    if (idx >= R_ * D_) return;
    int row = idx >> 7;
    int d   = idx & 127;
    int t   = row & (T_ - 1);
    const float* f = feat + (size_t)row * 3;
    float xv = fmaf(f[0], hw[d],
               fmaf(f[1], hw[D_ + d],
               fmaf(f[2], hw[2 * D_ + d], hb[d])));
    d_x[idx] = xv;
    int j2 = d & ~1;  // 2*j
    float ang = (float)t * __expf(-9.210340371976184f * (float)j2 / 128.0f);
    float pe = (d & 1) ? cosf(ang) : sinf(ang);
    d_oute[idx] = xv + pe;
}

// ---------------- kernel 2: tiled SGEMM, C = A(MxK) @ W(KxN) + bias, optional ReLU
// BM=BN=128, BK=8, 256 threads, 8x8 microtile. M%128==0, N%128==0, K%8==0.
#define BM 128
#define BN 128
#define BK 8
__global__ __launch_bounds__(256, 2)
void sgemm_kernel(const float* __restrict__ A, const float* __restrict__ W,
                  const float* __restrict__ bias, float* __restrict__ C,
                  int M, int N, int K, int relu)
{
    __shared__ float As[BK][BM];
    __shared__ float Bs[BK][BN];
    int bn0 = blockIdx.x * BN;
    int bm0 = blockIdx.y * BM;
    int tid = threadIdx.x;

    int aRow = tid >> 1;          // 0..127
    int aCol = (tid & 1) * 4;     // 0 or 4
    int bRow = tid >> 5;          // 0..7
    int bCol = (tid & 31) * 4;    // 0..124

    int ty = tid >> 4;            // 0..15
    int tx = tid & 15;            // 0..15

    float acc[8][8];
#pragma unroll
    for (int i = 0; i < 8; i++)
#pragma unroll
        for (int j = 0; j < 8; j++) acc[i][j] = 0.0f;

    for (int k0 = 0; k0 < K; k0 += BK) {
        float4 a4 = *(const float4*)(A + (size_t)(bm0 + aRow) * K + k0 + aCol);
        As[aCol + 0][aRow] = a4.x;
        As[aCol + 1][aRow] = a4.y;
        As[aCol + 2][aRow] = a4.z;
        As[aCol + 3][aRow] = a4.w;
        float4 b4 = *(const float4*)(W + (size_t)(k0 + bRow) * N + bn0 + bCol);
        *(float4*)&Bs[bRow][bCol] = b4;
        __syncthreads();
#pragma unroll
        for (int k = 0; k < BK; k++) {
            float a[8], b[8];
#pragma unroll
            for (int i = 0; i < 8; i++) a[i] = As[k][ty * 8 + i];
#pragma unroll
            for (int j = 0; j < 8; j++) b[j] = Bs[k][tx * 8 + j];
#pragma unroll
            for (int i = 0; i < 8; i++)
#pragma unroll
                for (int j = 0; j < 8; j++) acc[i][j] = fmaf(a[i], b[j], acc[i][j]);
        }
        __syncthreads();
    }
#pragma unroll
    for (int i = 0; i < 8; i++) {
        int r = bm0 + ty * 8 + i;
#pragma unroll
        for (int j = 0; j < 8; j++) {
            int c = bn0 + tx * 8 + j;
            float v = acc[i][j] + bias[c];
            if (relu) v = fmaxf(v, 0.0f);
            C[(size_t)r * N + c] = v;
        }
    }
}

// ---------------- kernel 3: attention per (b,n,h) block; writes O in-place over Q
__global__ __launch_bounds__(128)
void attn_kernel(float* __restrict__ q, const float* __restrict__ k,
                 const float* __restrict__ v)
{
    int blk = blockIdx.x;           // b*NA*H + n*H + h
    int h   = blk % H_;
    int bn  = blk / H_;             // b*NA + n
    const float* kb = k + (size_t)bn * T_ * D_;
    const float* vb = v + (size_t)bn * T_ * D_;

    __shared__ float Ks[T_][DH_];
    __shared__ float Vs[T_][DH_];
    int tid = threadIdx.x;          // 0..127, one query row each
    for (int i = tid; i < T_ * DH_; i += 128) {
        int r = i >> 4, c = i & 15;
        Ks[r][c] = kb[(size_t)r * D_ + h * DH_ + c];
        Vs[r][c] = vb[(size_t)r * D_ + h * DH_ + c];
    }
    __syncthreads();

    float* qrow = q + (size_t)bn * T_ * D_ + (size_t)tid * D_ + h * DH_;
    const float scale = 0.25f;      // 1/sqrt(16)
    float qr[DH_];
#pragma unroll
    for (int d = 0; d < DH_; d++) qr[d] = qrow[d] * scale;

    float m = -INFINITY, l = 0.0f;
    float acc[DH_];
#pragma unroll
    for (int d = 0; d < DH_; d++) acc[d] = 0.0f;

    for (int kk = 0; kk < T_; kk++) {
        float sc = 0.0f;
#pragma unroll
        for (int d = 0; d < DH_; d++) sc = fmaf(qr[d], Ks[kk][d], sc);
        float mn = fmaxf(m, sc);
        float corr = __expf(m - mn);
        float p = __expf(sc - mn);
        l = l * corr + p;
#pragma unroll
        for (int d = 0; d < DH_; d++) acc[d] = fmaf(acc[d], corr, p * Vs[kk][d]);
        m = mn;
    }
    float inv = 1.0f / l;
#pragma unroll
    for (int d = 0; d < DH_; d++) qrow[d] = acc[d] * inv;
}

// ---------------- kernel 4: out = LayerNorm(a + c) * g + b, one warp per row ----
__global__ void add_ln_kernel(const float* __restrict__ a, const float* __restrict__ c,
                              const float* __restrict__ g, const float* __restrict__ bb,
                              float* __restrict__ out)
{
    int warp = (blockIdx.x * blockDim.x + threadIdx.x) >> 5;
    int lane = threadIdx.x & 31;
    if (warp >= R_) return;
    size_t base = (size_t)warp * D_ + lane * 4;
    float4 av = *(const float4*)(a + base);
    float4 cv = *(const float4*)(c + base);
    float h0 = av.x + cv.x, h1 = av.y + cv.y, h2 = av.z + cv.z, h3 = av.w + cv.w;
    float sum = h0 + h1 + h2 + h3;
#pragma unroll
    for (int o = 16; o; o >>= 1) sum += __shfl_xor_sync(0xffffffffu, sum, o);
    float mu = sum * (1.0f / 128.0f);
    float e0 = h0 - mu, e1 = h1 - mu, e2 = h2 - mu, e3 = h3 - mu;
    float vs = e0 * e0 + e1 * e1 + e2 * e2 + e3 * e3;
#pragma unroll
    for (int o = 16; o; o >>= 1) vs += __shfl_xor_sync(0xffffffffu, vs, o);
    float inv = rsqrtf(vs * (1.0f / 128.0f) + EPSV);
    float4 gv = *(const float4*)(g + lane * 4);
    float4 bv = *(const float4*)(bb + lane * 4);
    float4 r;
    r.x = e0 * inv * gv.x + bv.x;
    r.y = e1 * inv * gv.y + bv.y;
    r.z = e2 * inv * gv.z + bv.z;
    r.w = e3 * inv * gv.w + bv.w;
    *(float4*)(out + base) = r;
}

// ---------------- kernel 5: s[b, t*NA+n] = dot(out_e[b,n,t,:], x[b,n,t,:]) ------
__global__ void sdot_kernel()
{
    int warp = (blockIdx.x * blockDim.x + threadIdx.x) >> 5;
    int lane = threadIdx.x & 31;
    if (warp >= R_) return;
    size_t base = (size_t)warp * D_ + lane * 4;
    float4 w4 = *(const float4*)(d_oute + base);
    float4 x4 = *(const float4*)(d_x + base);
    float dt = w4.x * x4.x + w4.y * x4.y + w4.z * x4.z + w4.w * x4.w;
#pragma unroll
    for (int o = 16; o; o >>= 1) dt += __shfl_xor_sync(0xffffffffu, dt, o);
    if (lane == 0) {
        int b = warp / (NA_ * T_);
        int rem = warp % (NA_ * T_);
        int n = rem / T_;
        int t = rem % T_;
        d_s[b * NN_ + t * NA_ + n] = dt;
    }
}

// ---------------- kernel 6: zero accumulators ------------------------------------
__global__ void zero_kernel()
{
    int i = blockIdx.x * blockDim.x + threadIdx.x;
    if (i < B_ * NN_) d_g[i] = 0.0f;
    if (i < 2) d_stats[i] = 0.0;
}

// ---------------- kernel 7: edge aggregation -------------------------------------
__global__ void edge_kernel(const int* __restrict__ ei, const float* __restrict__ ew)
{
    int gid = blockIdx.x * blockDim.x + threadIdx.x;
    if (gid >= B_ * E_) return;
    int b = gid / E_;
    int e = gid % E_;
    const int* eb = ei + (size_t)b * 2 * E_;
    int src = eb[e];
    int dst = eb[E_ + e];
    atomicAdd(&d_g[b * NN_ + dst], ew[(size_t)b * E_ + e] * d_s[b * NN_ + src]);
}

// ---------------- kernel 8: global batchnorm stats (double precision) ------------
__global__ void bnstats_kernel()
{
    double s = 0.0, sq = 0.0;
    for (int i = blockIdx.x * blockDim.x + threadIdx.x; i < B_ * NN_;
         i += gridDim.x * blockDim.x) {
        double v = (double)d_g[i];
        s += v; sq += v * v;
    }
#pragma unroll
    for (int o = 16; o; o >>= 1) {
        s  += __shfl_xor_sync(0xffffffffu, s, o);
        sq += __shfl_xor_sync(0xffffffffu, sq, o);
    }
    if ((threadIdx.x & 31) == 0) {
        atomicAdd(&d_stats[0], s);
        atomicAdd(&d_stats[1], sq);
    }
}

// ---------------- kernel 9: final outer product ----------------------------------
// out[b,n,t,d] = ((g[b,t,n]-mu)*rsqrt(var+eps)*bn_g + bn_b) * lin_w[d] + lin_b[d]
__global__ void final_kernel(const float* __restrict__ bng, const float* __restrict__ bnb,
                             const float* __restrict__ lw, const float* __restrict__ lb,
                             float* __restrict__ out)
{
    int idx = blockIdx.x * blockDim.x + threadIdx.x;
    if (idx >= R_ * D_) return;
    int d   = idx & 127;
    int row = idx >> 7;            // (b*NA + n)*T + t
    int t   = row & 127;
    int bn  = row >> 7;            // b*NA + n
    int b   = bn >> 6;
    int n   = bn & 63;
    double mu  = d_stats[0] * (1.0 / 32768.0);
    double var = d_stats[1] * (1.0 / 32768.0) - mu * mu;
    float inv = rsqrtf((float)var + EPSV);
    float gval = d_g[b * NN_ + t * NA_ + n];
    float ghat = ((gval - (float)mu) * inv) * bng[0] + bnb[0];
    out[idx] = ghat * lw[d] + lb[d];
}

// ---------------- launcher -------------------------------------------------------
static inline void run_gemm(const float* A, const float* W, const float* bias,
                            float* C, int M, int N, int K, int relu)
{
    dim3 grid(N / BN, M / BM);
    sgemm_kernel<<<grid, 256>>>(A, W, bias, C, M, N, K, relu);
}

extern "C" void kernel_launch(void* const* d_in, const int* in_sizes, int n_in,
                              void* d_out, int out_size)
{
    const float* feat    = (const float*)d_in[0];
    const int*   eindex  = (const int*)  d_in[1];
    const float* eweight = (const float*)d_in[2];
    const float* hist_w  = (const float*)d_in[3];
    const float* hist_b  = (const float*)d_in[4];
    const float* wq      = (const float*)d_in[5];
    const float* bq      = (const float*)d_in[6];
    const float* wk      = (const float*)d_in[7];
    const float* bk      = (const float*)d_in[8];
    const float* wv      = (const float*)d_in[9];
    const float* bv      = (const float*)d_in[10];
    const float* wo      = (const float*)d_in[11];
    const float* bo      = (const float*)d_in[12];
    const float* ln1g    = (const float*)d_in[13];
    const float* ln1b    = (const float*)d_in[14];
    const float* fw1     = (const float*)d_in[15];
    const float* fb1     = (const float*)d_in[16];
    const float* fw2     = (const float*)d_in[17];
    const float* fb2     = (const float*)d_in[18];
    const float* ln2g    = (const float*)d_in[19];
    const float* ln2b    = (const float*)d_in[20];
    const float* bng     = (const float*)d_in[21];
    const float* bnb     = (const float*)d_in[22];
    const float* linw    = (const float*)d_in[23];
    const float* linb    = (const float*)d_in[24];
    float* out = (float*)d_out;

    float* px    = nullptr; cudaGetSymbolAddress((void**)&px,    d_x);
    float* poute = nullptr; cudaGetSymbolAddress((void**)&poute, d_oute);
    float* pq    = nullptr; cudaGetSymbolAddress((void**)&pq,    d_q);
    float* pk    = nullptr; cudaGetSymbolAddress((void**)&pk,    d_k);
    float* pv    = nullptr; cudaGetSymbolAddress((void**)&pv,    d_v);
    float* ph1   = nullptr; cudaGetSymbolAddress((void**)&ph1,   d_h1);
    float* ptmp  = nullptr; cudaGetSymbolAddress((void**)&ptmp,  d_tmp);
    float* pff   = nullptr; cudaGetSymbolAddress((void**)&pff,   d_ff);

    const int TPB = 256;

    // 1. x + positional encoding
    hist_pe_kernel<<<(R_ * D_ + TPB - 1) / TPB, TPB>>>(feat, hist_w, hist_b);

    // 2. transformer layers
    for (int l = 0; l < L_; l++) {
        const float* wql = wq + (size_t)l * D_ * D_;
        const float* wkl = wk + (size_t)l * D_ * D_;
        const float* wvl = wv + (size_t)l * D_ * D_;
        const float* wol = wo + (size_t)l * D_ * D_;
        run_gemm(poute, wql, bq + l * D_, pq, R_, D_, D_, 0);
        run_gemm(poute, wkl, bk + l * D_, pk, R_, D_, D_, 0);
        run_gemm(poute, wvl, bv + l * D_, pv, R_, D_, D_, 0);
        attn_kernel<<<B_ * NA_ * H_, 128>>>(pq, pk, pv);
        run_gemm(pq, wol, bo + l * D_, ptmp, R_, D_, D_, 0);
        add_ln_kernel<<<(R_ * 32 + TPB - 1) / TPB, TPB>>>(poute, ptmp,
                                                          ln1g + l * D_, ln1b + l * D_, ph1);
        run_gemm(ph1, fw1 + (size_t)l * D_ * DFF_, fb1 + l * DFF_, pff, R_, DFF_, D_, 1);
        run_gemm(pff, fw2 + (size_t)l * DFF_ * D_, fb2 + l * D_, ptmp, R_, D_, DFF_, 0);
        add_ln_kernel<<<(R_ * 32 + TPB - 1) / TPB, TPB>>>(ph1, ptmp,
                                                          ln2g + l * D_, ln2b + l * D_, poute);
    }

    // 3. scoring dot products
    sdot_kernel<<<(R_ * 32 + TPB - 1) / TPB, TPB>>>();

    // 4. edge aggregation
    zero_kernel<<<(B_ * NN_ + TPB - 1) / TPB, TPB>>>();
    edge_kernel<<<(B_ * E_ + TPB - 1) / TPB, TPB>>>(eindex, eweight);

    // 5. global batchnorm stats + final outer product
    bnstats_kernel<<<64, TPB>>>();
    final_kernel<<<(R_ * D_ + TPB - 1) / TPB, TPB>>>(bng, bnb, linw, linb, out);
}

// round 3
// speedup vs baseline: 1.4481x; 1.4481x over previous
#include <cuda_runtime.h>
#include <cstdint>
#include <math.h>

// Problem constants
#define B_   4
#define NA_  64
#define T_   128
#define D_   128
#define H_   8
#define DH_  16
#define L_   3
#define DFF_ 512
#define E_   65536
#define NN_  (T_ * NA_)        // 8192
#define R_   (B_ * NA_ * T_)   // 32768 rows
#define EPSV 1e-5f

// ---------------- scratch (device globals; no allocation allowed) ----------------
__device__ __align__(256) float d_x   [R_ * D_];
__device__ __align__(256) float d_oute[R_ * D_];
__device__ __align__(256) float d_q   [R_ * D_];
__device__ __align__(256) float d_k   [R_ * D_];
__device__ __align__(256) float d_v   [R_ * D_];
__device__ __align__(256) float d_h1  [R_ * D_];
__device__ __align__(256) float d_tmp [R_ * D_];
__device__ __align__(256) float d_ff  [R_ * DFF_];
__device__ __align__(256) float d_s   [B_ * NN_];
__device__ __align__(256) float d_g   [B_ * NN_];
__device__ double d_stats[2];

// ---------------- tf32 helpers ---------------------------------------------------
__device__ __forceinline__ float tf32_round(float x) {
    uint32_t u;
    asm("cvt.rna.tf32.f32 %0, %1;" : "=r"(u) : "f"(x));
    return __uint_as_float(u);
}

__device__ __forceinline__ void mma_tf32(float* c, const uint32_t* a, const uint32_t* b) {
    asm volatile(
        "mma.sync.aligned.m16n8k8.row.col.f32.tf32.tf32.f32 "
        "{%0,%1,%2,%3}, {%4,%5,%6,%7}, {%8,%9}, {%0,%1,%2,%3};"
        : "+f"(c[0]), "+f"(c[1]), "+f"(c[2]), "+f"(c[3])
        : "r"(a[0]), "r"(a[1]), "r"(a[2]), "r"(a[3]), "r"(b[0]), "r"(b[1]));
}

// ---------------- tensor-core split-tf32 GEMM: C = A(MxK) @ W(KxN) + bias --------
// CTA tile 128x128, BK=32, 256 threads (8 warps, each 32m x 64n).
#define SA 36
#define SB 132
#define GEMM_SMEM ((2 * 128 * SA + 2 * 32 * SB) * 4)   // 70656 bytes

__global__ void __launch_bounds__(256, 1)
tf32_gemm_kernel(const float* __restrict__ A, const float* __restrict__ W,
                 const float* __restrict__ bias, float* __restrict__ C,
                 int K, int N, int relu)
{
    extern __shared__ float sm[];
    float* Ah = sm;
    float* Al = Ah + 128 * SA;
    float* Bh = Al + 128 * SA;
    float* Bl = Bh + 32 * SB;

    int tid = threadIdx.x;
    int wid = tid >> 5;
    int lane = tid & 31;
    int g  = lane >> 2;     // group id (row within frag)
    int tg = lane & 3;      // thread-in-group (col within frag)
    int warp_m = wid & 3;   // 0..3 -> 32-row band
    int warp_n = wid >> 2;  // 0..1 -> 64-col band
    int bm0 = blockIdx.y * 128;
    int bn0 = blockIdx.x * 128;

    float acc[2][8][4];
#pragma unroll
    for (int mt = 0; mt < 2; mt++)
#pragma unroll
        for (int nt = 0; nt < 8; nt++)
#pragma unroll
            for (int j = 0; j < 4; j++) acc[mt][nt][j] = 0.0f;

    for (int kc = 0; kc < K; kc += 32) {
        // ---- fill A tile (128x32) split hi/lo ----
#pragma unroll
        for (int i = 0; i < 4; i++) {
            int li = i * 256 + tid;
            int r = li >> 3;
            int c = (li & 7) * 4;
            float4 a4 = *(const float4*)(A + (size_t)(bm0 + r) * K + kc + c);
            float4 h, l;
            h.x = tf32_round(a4.x); l.x = a4.x - h.x;
            h.y = tf32_round(a4.y); l.y = a4.y - h.y;
            h.z = tf32_round(a4.z); l.z = a4.z - h.z;
            h.w = tf32_round(a4.w); l.w = a4.w - h.w;
            *(float4*)(Ah + r * SA + c) = h;
            *(float4*)(Al + r * SA + c) = l;
        }
        // ---- fill B tile (32x128) split hi/lo ----
#pragma unroll
        for (int i = 0; i < 4; i++) {
            int li = i * 256 + tid;
            int r = li >> 5;
            int c = (li & 31) * 4;
            float4 b4 = *(const float4*)(W + (size_t)(kc + r) * N + bn0 + c);
            float4 h, l;
            h.x = tf32_round(b4.x); l.x = b4.x - h.x;
            h.y = tf32_round(b4.y); l.y = b4.y - h.y;
            h.z = tf32_round(b4.z); l.z = b4.z - h.z;
            h.w = tf32_round(b4.w); l.w = b4.w - h.w;
            *(float4*)(Bh + r * SB + c) = h;
            *(float4*)(Bl + r * SB + c) = l;
        }
        __syncthreads();

#pragma unroll
        for (int ks = 0; ks < 4; ks++) {
            uint32_t afh[2][4], afl[2][4];
#pragma unroll
            for (int mt = 0; mt < 2; mt++) {
                int r0 = warp_m * 32 + mt * 16 + g;
                int c0 = ks * 8 + tg;
                afh[mt][0] = __float_as_uint(Ah[r0 * SA + c0]);
                afh[mt][1] = __float_as_uint(Ah[(r0 + 8) * SA + c0]);
                afh[mt][2] = __float_as_uint(Ah[r0 * SA + c0 + 4]);
                afh[mt][3] = __float_as_uint(Ah[(r0 + 8) * SA + c0 + 4]);
                afl[mt][0] = __float_as_uint(Al[r0 * SA + c0]);
                afl[mt][1] = __float_as_uint(Al[(r0 + 8) * SA + c0]);
                afl[mt][2] = __float_as_uint(Al[r0 * SA + c0 + 4]);
                afl[mt][3] = __float_as_uint(Al[(r0 + 8) * SA + c0 + 4]);
            }
            uint32_t bfh[8][2], bfl[8][2];
#pragma unroll
            for (int nt = 0; nt < 8; nt++) {
                int kk = ks * 8 + tg;
                int n0 = warp_n * 64 + nt * 8 + g;
                bfh[nt][0] = __float_as_uint(Bh[kk * SB + n0]);
                bfh[nt][1] = __float_as_uint(Bh[(kk + 4) * SB + n0]);
                bfl[nt][0] = __float_as_uint(Bl[kk * SB + n0]);
                bfl[nt][1] = __float_as_uint(Bl[(kk + 4) * SB + n0]);
            }
#pragma unroll
            for (int mt = 0; mt < 2; mt++)
#pragma unroll
                for (int nt = 0; nt < 8; nt++) {
                    mma_tf32(acc[mt][nt], afh[mt], bfh[nt]);
                    mma_tf32(acc[mt][nt], afh[mt], bfl[nt]);
                    mma_tf32(acc[mt][nt], afl[mt], bfh[nt]);
                }
        }
        __syncthreads();
    }

    // ---- epilogue: bias (+ReLU), direct global stores ----
#pragma unroll
    for (int mt = 0; mt < 2; mt++) {
        int r0 = bm0 + warp_m * 32 + mt * 16 + g;
#pragma unroll
        for (int nt = 0; nt < 8; nt++) {
            int c0 = bn0 + warp_n * 64 + nt * 8 + tg * 2;
            float b0 = bias[c0], b1 = bias[c0 + 1];
            float v0 = acc[mt][nt][0] + b0;
            float v1 = acc[mt][nt][1] + b1;
            float v2 = acc[mt][nt][2] + b0;
            float v3 = acc[mt][nt][3] + b1;
            if (relu) {
                v0 = fmaxf(v0, 0.0f); v1 = fmaxf(v1, 0.0f);
                v2 = fmaxf(v2, 0.0f); v3 = fmaxf(v3, 0.0f);
            }
            *(float2*)(C + (size_t)r0 * N + c0)       = make_float2(v0, v1);
            *(float2*)(C + (size_t)(r0 + 8) * N + c0) = make_float2(v2, v3);
        }
    }
}

// ---------------- kernel 1: hist projection + positional encoding ----------------
__global__ void hist_pe_kernel(const float* __restrict__ feat,
                               const float* __restrict__ hw,
                               const float* __restrict__ hb)
{
    int idx = blockIdx.x * blockDim.x + threadIdx.x;
    if (idx >= R_ * D_) return;
    int row = idx >> 7;
    int d   = idx & 127;
    int t   = row & (T_ - 1);
    const float* f = feat + (size_t)row * 3;
    float xv = fmaf(f[0], hw[d],
               fmaf(f[1], hw[D_ + d],
               fmaf(f[2], hw[2 * D_ + d], hb[d])));
    d_x[idx] = xv;
    int j2 = d & ~1;
    float ang = (float)t * __expf(-9.210340371976184f * (float)j2 / 128.0f);
    float pe = (d & 1) ? cosf(ang) : sinf(ang);
    d_oute[idx] = xv + pe;
}

// ---------------- attention per (b,n,h) block; writes O in-place over Q ---------
__global__ __launch_bounds__(128)
void attn_kernel(float* __restrict__ q, const float* __restrict__ k,
                 const float* __restrict__ v)
{
    int blk = blockIdx.x;
    int h   = blk % H_;
    int bn  = blk / H_;
    const float* kb = k + (size_t)bn * T_ * D_;
    const float* vb = v + (size_t)bn * T_ * D_;

    __shared__ float Ks[T_][DH_];
    __shared__ float Vs[T_][DH_];
    int tid = threadIdx.x;
    for (int i = tid; i < T_ * DH_; i += 128) {
        int r = i >> 4, c = i & 15;
        Ks[r][c] = kb[(size_t)r * D_ + h * DH_ + c];
        Vs[r][c] = vb[(size_t)r * D_ + h * DH_ + c];
    }
    __syncthreads();

    float* qrow = q + (size_t)bn * T_ * D_ + (size_t)tid * D_ + h * DH_;
    const float scale = 0.25f;
    float qr[DH_];
#pragma unroll
    for (int d = 0; d < DH_; d++) qr[d] = qrow[d] * scale;

    float m = -INFINITY, l = 0.0f;
    float acc[DH_];
#pragma unroll
    for (int d = 0; d < DH_; d++) acc[d] = 0.0f;

    for (int kk = 0; kk < T_; kk++) {
        float sc = 0.0f;
#pragma unroll
        for (int d = 0; d < DH_; d++) sc = fmaf(qr[d], Ks[kk][d], sc);
        float mn = fmaxf(m, sc);
        float corr = __expf(m - mn);
        float p = __expf(sc - mn);
        l = l * corr + p;
#pragma unroll
        for (int d = 0; d < DH_; d++) acc[d] = fmaf(acc[d], corr, p * Vs[kk][d]);
        m = mn;
    }
    float inv = 1.0f / l;
#pragma unroll
    for (int d = 0; d < DH_; d++) qrow[d] = acc[d] * inv;
}

// ---------------- out = LayerNorm(a + c) * g + b, one warp per row --------------
__global__ void add_ln_kernel(const float* __restrict__ a, const float* __restrict__ c,
                              const float* __restrict__ g, const float* __restrict__ bb,
                              float* __restrict__ out)
{
    int warp = (blockIdx.x * blockDim.x + threadIdx.x) >> 5;
    int lane = threadIdx.x & 31;
    if (warp >= R_) return;
    size_t base = (size_t)warp * D_ + lane * 4;
    float4 av = *(const float4*)(a + base);
    float4 cv = *(const float4*)(c + base);
    float h0 = av.x + cv.x, h1 = av.y + cv.y, h2 = av.z + cv.z, h3 = av.w + cv.w;
    float sum = h0 + h1 + h2 + h3;
#pragma unroll
    for (int o = 16; o; o >>= 1) sum += __shfl_xor_sync(0xffffffffu, sum, o);
    float mu = sum * (1.0f / 128.0f);
    float e0 = h0 - mu, e1 = h1 - mu, e2 = h2 - mu, e3 = h3 - mu;
    float vs = e0 * e0 + e1 * e1 + e2 * e2 + e3 * e3;
#pragma unroll
    for (int o = 16; o; o >>= 1) vs += __shfl_xor_sync(0xffffffffu, vs, o);
    float inv = rsqrtf(vs * (1.0f / 128.0f) + EPSV);
    float4 gv = *(const float4*)(g + lane * 4);
    float4 bv = *(const float4*)(bb + lane * 4);
    float4 r;
    r.x = e0 * inv * gv.x + bv.x;
    r.y = e1 * inv * gv.y + bv.y;
    r.z = e2 * inv * gv.z + bv.z;
    r.w = e3 * inv * gv.w + bv.w;
    *(float4*)(out + base) = r;
}

// ---------------- s[b, t*NA+n] = dot(out_e[b,n,t,:], x[b,n,t,:]) ----------------
__global__ void sdot_kernel()
{
    int warp = (blockIdx.x * blockDim.x + threadIdx.x) >> 5;
    int lane = threadIdx.x & 31;
    if (warp >= R_) return;
    size_t base = (size_t)warp * D_ + lane * 4;
    float4 w4 = *(const float4*)(d_oute + base);
    float4 x4 = *(const float4*)(d_x + base);
    float dt = w4.x * x4.x + w4.y * x4.y + w4.z * x4.z + w4.w * x4.w;
#pragma unroll
    for (int o = 16; o; o >>= 1) dt += __shfl_xor_sync(0xffffffffu, dt, o);
    if (lane == 0) {
        int b = warp / (NA_ * T_);
        int rem = warp % (NA_ * T_);
        int n = rem / T_;
        int t = rem % T_;
        d_s[b * NN_ + t * NA_ + n] = dt;
    }
}

// ---------------- zero accumulators ---------------------------------------------
__global__ void zero_kernel()
{
    int i = blockIdx.x * blockDim.x + threadIdx.x;
    if (i < B_ * NN_) d_g[i] = 0.0f;
    if (i < 2) d_stats[i] = 0.0;
}

// ---------------- edge aggregation ----------------------------------------------
__global__ void edge_kernel(const int* __restrict__ ei, const float* __restrict__ ew)
{
    int gid = blockIdx.x * blockDim.x + threadIdx.x;
    if (gid >= B_ * E_) return;
    int b = gid / E_;
    int e = gid % E_;
    const int* eb = ei + (size_t)b * 2 * E_;
    int src = eb[e];
    int dst = eb[E_ + e];
    atomicAdd(&d_g[b * NN_ + dst], ew[(size_t)b * E_ + e] * d_s[b * NN_ + src]);
}

// ---------------- global batchnorm stats (double precision) ---------------------
__global__ void bnstats_kernel()
{
    double s = 0.0, sq = 0.0;
    for (int i = blockIdx.x * blockDim.x + threadIdx.x; i < B_ * NN_;
         i += gridDim.x * blockDim.x) {
        double v = (double)d_g[i];
        s += v; sq += v * v;
    }
#pragma unroll
    for (int o = 16; o; o >>= 1) {
        s  += __shfl_xor_sync(0xffffffffu, s, o);
        sq += __shfl_xor_sync(0xffffffffu, sq, o);
    }
    if ((threadIdx.x & 31) == 0) {
        atomicAdd(&d_stats[0], s);
        atomicAdd(&d_stats[1], sq);
    }
}

// ---------------- final outer product -------------------------------------------
__global__ void final_kernel(const float* __restrict__ bng, const float* __restrict__ bnb,
                             const float* __restrict__ lw, const float* __restrict__ lb,
                             float* __restrict__ out)
{
    int idx = blockIdx.x * blockDim.x + threadIdx.x;
    if (idx >= R_ * D_) return;
    int d   = idx & 127;
    int row = idx >> 7;
    int t   = row & 127;
    int bn  = row >> 7;
    int b   = bn >> 6;
    int n   = bn & 63;
    double mu  = d_stats[0] * (1.0 / 32768.0);
    double var = d_stats[1] * (1.0 / 32768.0) - mu * mu;
    float inv = rsqrtf((float)var + EPSV);
    float gval = d_g[b * NN_ + t * NA_ + n];
    float ghat = ((gval - (float)mu) * inv) * bng[0] + bnb[0];
    out[idx] = ghat * lw[d] + lb[d];
}

// ---------------- launcher -------------------------------------------------------
static inline void run_gemm(const float* A, const float* W, const float* bias,
                            float* C, int M, int N, int K, int relu)
{
    cudaFuncSetAttribute(tf32_gemm_kernel,
                         cudaFuncAttributeMaxDynamicSharedMemorySize, GEMM_SMEM);
    dim3 grid(N / 128, M / 128);
    tf32_gemm_kernel<<<grid, 256, GEMM_SMEM>>>(A, W, bias, C, K, N, relu);
}

extern "C" void kernel_launch(void* const* d_in, const int* in_sizes, int n_in,
                              void* d_out, int out_size)
{
    const float* feat    = (const float*)d_in[0];
    const int*   eindex  = (const int*)  d_in[1];
    const float* eweight = (const float*)d_in[2];
    const float* hist_w  = (const float*)d_in[3];
    const float* hist_b  = (const float*)d_in[4];
    const float* wq      = (const float*)d_in[5];
    const float* bq      = (const float*)d_in[6];
    const float* wk      = (const float*)d_in[7];
    const float* bk      = (const float*)d_in[8];
    const float* wv      = (const float*)d_in[9];
    const float* bv      = (const float*)d_in[10];
    const float* wo      = (const float*)d_in[11];
    const float* bo      = (const float*)d_in[12];
    const float* ln1g    = (const float*)d_in[13];
    const float* ln1b    = (const float*)d_in[14];
    const float* fw1     = (const float*)d_in[15];
    const float* fb1     = (const float*)d_in[16];
    const float* fw2     = (const float*)d_in[17];
    const float* fb2     = (const float*)d_in[18];
    const float* ln2g    = (const float*)d_in[19];
    const float* ln2b    = (const float*)d_in[20];
    const float* bng     = (const float*)d_in[21];
    const float* bnb     = (const float*)d_in[22];
    const float* linw    = (const float*)d_in[23];
    const float* linb    = (const float*)d_in[24];
    float* out = (float*)d_out;

    float* px    = nullptr; cudaGetSymbolAddress((void**)&px,    d_x);
    float* poute = nullptr; cudaGetSymbolAddress((void**)&poute, d_oute);
    float* pq    = nullptr; cudaGetSymbolAddress((void**)&pq,    d_q);
    float* pk    = nullptr; cudaGetSymbolAddress((void**)&pk,    d_k);
    float* pv    = nullptr; cudaGetSymbolAddress((void**)&pv,    d_v);
    float* ph1   = nullptr; cudaGetSymbolAddress((void**)&ph1,   d_h1);
    float* ptmp  = nullptr; cudaGetSymbolAddress((void**)&ptmp,  d_tmp);
    float* pff   = nullptr; cudaGetSymbolAddress((void**)&pff,   d_ff);

    const int TPB = 256;

    // 1. x + positional encoding
    hist_pe_kernel<<<(R_ * D_ + TPB - 1) / TPB, TPB>>>(feat, hist_w, hist_b);

    // 2. transformer layers
    for (int l = 0; l < L_; l++) {
        const float* wql = wq + (size_t)l * D_ * D_;
        const float* wkl = wk + (size_t)l * D_ * D_;
        const float* wvl = wv + (size_t)l * D_ * D_;
        const float* wol = wo + (size_t)l * D_ * D_;
        run_gemm(poute, wql, bq + l * D_, pq, R_, D_, D_, 0);
        run_gemm(poute, wkl, bk + l * D_, pk, R_, D_, D_, 0);
        run_gemm(poute, wvl, bv + l * D_, pv, R_, D_, D_, 0);
        attn_kernel<<<B_ * NA_ * H_, 128>>>(pq, pk, pv);
        run_gemm(pq, wol, bo + l * D_, ptmp, R_, D_, D_, 0);
        add_ln_kernel<<<(R_ * 32 + TPB - 1) / TPB, TPB>>>(poute, ptmp,
                                                          ln1g + l * D_, ln1b + l * D_, ph1);
        run_gemm(ph1, fw1 + (size_t)l * D_ * DFF_, fb1 + l * DFF_, pff, R_, DFF_, D_, 1);
        run_gemm(pff, fw2 + (size_t)l * DFF_ * D_, fb2 + l * D_, ptmp, R_, D_, DFF_, 0);
        add_ln_kernel<<<(R_ * 32 + TPB - 1) / TPB, TPB>>>(ph1, ptmp,
                                                          ln2g + l * D_, ln2b + l * D_, poute);
    }

    // 3. scoring dot products
    sdot_kernel<<<(R_ * 32 + TPB - 1) / TPB, TPB>>>();

    // 4. edge aggregation
    zero_kernel<<<(B_ * NN_ + TPB - 1) / TPB, TPB>>>();
    edge_kernel<<<(B_ * E_ + TPB - 1) / TPB, TPB>>>(eindex, eweight);

    // 5. global batchnorm stats + final outer product
    bnstats_kernel<<<64, TPB>>>();
    final_kernel<<<(R_ * D_ + TPB - 1) / TPB, TPB>>>(bng, bnb, linw, linb, out);
}